// round 4
// baseline (speedup 1.0000x reference)
#include <cuda_runtime.h>
#include <cstdint>

// Problem shapes (fixed by the dataset)
#define NMAX 100000
#define EMAX 600000
#define HDIM 128
#define GMAXX 512

// Scratch (allocation-free rule: __device__ globals)
__device__ float g_buf1[(size_t)NMAX * HDIM];   // GEMM outputs
__device__ float g_buf2[(size_t)NMAX * HDIM];   // aggregation / hidden
__device__ float g_deg[NMAX];
__device__ float g_dis[NMAX];
__device__ float g_norm[EMAX];
__device__ int   g_src[EMAX];
__device__ int   g_dst[EMAX];
__device__ float g_pool[(size_t)GMAXX * HDIM];
__device__ float g_cnt[GMAXX];

// ---------------------------------------------------------------------------
// K1: init deg=1 (self loop), zero pool sums + counts
__global__ void k_init(int N, int G) {
    int i = blockIdx.x * blockDim.x + threadIdx.x;
    if (i < N) g_deg[i] = 1.0f;
    if (i < G * HDIM) g_pool[i] = 0.0f;
    if (i < G) g_cnt[i] = 0.0f;
}

// K2: copy edges (ALREADY int32 in the harness!), accumulate in-degree
__global__ void k_edges_deg(const int* __restrict__ ei, int E) {
    int i = blockIdx.x * blockDim.x + threadIdx.x;
    if (i >= E) return;
    int s = ei[i];
    int d = ei[(size_t)E + i];
    g_src[i] = s;
    g_dst[i] = d;
    atomicAdd(&g_deg[d], 1.0f);
}

// K3: dis = rsqrt(deg); also count nodes per graph (for mean pool)
__global__ void k_dis(const int* __restrict__ batch, int N) {
    int i = blockIdx.x * blockDim.x + threadIdx.x;
    if (i >= N) return;
    g_dis[i] = rsqrtf(g_deg[i]);   // deg >= 1 always (self loop)
    atomicAdd(&g_cnt[batch[i]], 1.0f);
}

// K4: per-edge norm
__global__ void k_norm(int E) {
    int i = blockIdx.x * blockDim.x + threadIdx.x;
    if (i >= E) return;
    g_norm[i] = g_dis[g_src[i]] * g_dis[g_dst[i]];
}

// ---------------------------------------------------------------------------
// GEMM: C[N,128] = A[N,128] @ W[128,128].  64-row blocks, full W in smem.
// 256 threads, each computes 8 rows x 4 cols.
__global__ void k_gemm(const float* __restrict__ A, const float* __restrict__ Wm,
                       float* __restrict__ C, int N) {
    extern __shared__ float sh[];
    float* sW = sh;                 // 128*128
    float* sA = sh + 128 * 128;     // 64*128
    int tid = threadIdx.x;
    int row0 = blockIdx.x * 64;

    // load W (4096 float4, 16 per thread)
    const float4* W4 = (const float4*)Wm;
    float4* sW4 = (float4*)sW;
#pragma unroll
    for (int i = 0; i < 16; i++) sW4[tid + 256 * i] = W4[tid + 256 * i];

    // load A tile (2048 float4, 8 per thread), guard rows
    const float4* A4 = (const float4*)A;
    float4* sA4 = (float4*)sA;
#pragma unroll
    for (int i = 0; i < 8; i++) {
        int idx = tid + 256 * i;        // 0..2047
        int r = idx >> 5;               // row within tile
        int c4 = idx & 31;
        float4 v = make_float4(0.f, 0.f, 0.f, 0.f);
        if (row0 + r < N) v = A4[(size_t)(row0 + r) * 32 + c4];
        sA4[idx] = v;
    }
    __syncthreads();

    int ty = tid >> 5;     // 0..7  (warp id) -> row group
    int tx = tid & 31;     // 0..31 -> 4-col group
    float acc[8][4];
#pragma unroll
    for (int i = 0; i < 8; i++)
#pragma unroll
        for (int j = 0; j < 4; j++) acc[i][j] = 0.f;

#pragma unroll 4
    for (int k = 0; k < 128; k++) {
        float4 w = ((const float4*)(sW + (size_t)k * 128))[tx];
#pragma unroll
        for (int i = 0; i < 8; i++) {
            float a = sA[(size_t)(ty + i * 8) * 128 + k];  // warp-broadcast
            acc[i][0] += a * w.x;
            acc[i][1] += a * w.y;
            acc[i][2] += a * w.z;
            acc[i][3] += a * w.w;
        }
    }

#pragma unroll
    for (int i = 0; i < 8; i++) {
        int r = row0 + ty + i * 8;
        if (r < N)
            ((float4*)(C + (size_t)r * 128))[tx] =
                make_float4(acc[i][0], acc[i][1], acc[i][2], acc[i][3]);
    }
}

// ---------------------------------------------------------------------------
// Self-loop contribution initializes the aggregation buffer (no atomics).
__global__ void k_self(const float* __restrict__ gm, float* __restrict__ agg, int N) {
    int i = blockIdx.x * blockDim.x + threadIdx.x;   // over N*32 float4s
    if (i >= N * 32) return;
    int node = i >> 5;
    float s = g_dis[node];
    s = s * s;
    float4 v = ((const float4*)gm)[i];
    ((float4*)agg)[i] = make_float4(v.x * s, v.y * s, v.z * s, v.w * s);
}

// Edge scatter: one warp per edge; coalesced 512B gather, scalar atomicAdd.
__global__ void k_scatter(const float* __restrict__ feat, float* __restrict__ agg, int E) {
    int gw = (blockIdx.x * blockDim.x + threadIdx.x) >> 5;
    int lane = threadIdx.x & 31;
    if (gw >= E) return;
    int s = g_src[gw];
    int d = g_dst[gw];
    float nrm = g_norm[gw];
    float4 v = ((const float4*)(feat + (size_t)s * 128))[lane];
    float* p = agg + (size_t)d * 128 + lane * 4;
    atomicAdd(p + 0, v.x * nrm);
    atomicAdd(p + 1, v.y * nrm);
    atomicAdd(p + 2, v.z * nrm);
    atomicAdd(p + 3, v.w * nrm);
}

// bias + relu in place (layer 1)
__global__ void k_relu_bias(float* __restrict__ agg, const float* __restrict__ bias, int N) {
    int i = blockIdx.x * blockDim.x + threadIdx.x;
    if (i >= N * 32) return;
    float4 b = ((const float4*)bias)[i & 31];
    float4 v = ((float4*)agg)[i];
    v.x = fmaxf(v.x + b.x, 0.f);
    v.y = fmaxf(v.y + b.y, 0.f);
    v.z = fmaxf(v.z + b.z, 0.f);
    v.w = fmaxf(v.w + b.w, 0.f);
    ((float4*)agg)[i] = v;
}

// layer 2 epilogue: bias + relu + mean-pool accumulation (no store of h2)
__global__ void k_relu_pool(const float* __restrict__ agg, const float* __restrict__ bias,
                            const int* __restrict__ batch, int N) {
    int node = (blockIdx.x * blockDim.x + threadIdx.x) >> 5;
    int lane = threadIdx.x & 31;
    if (node >= N) return;
    int g = batch[node];
    float4 b = ((const float4*)bias)[lane];
    float4 v = ((const float4*)(agg + (size_t)node * 128))[lane];
    v.x = fmaxf(v.x + b.x, 0.f);
    v.y = fmaxf(v.y + b.y, 0.f);
    v.z = fmaxf(v.z + b.z, 0.f);
    v.w = fmaxf(v.w + b.w, 0.f);
    float* p = g_pool + (size_t)g * 128 + lane * 4;
    atomicAdd(p + 0, v.x);
    atomicAdd(p + 1, v.y);
    atomicAdd(p + 2, v.z);
    atomicAdd(p + 3, v.w);
}

// final: out[g] = (pool[g]/cnt[g]) . Wfc + bfc
__global__ void k_final(const float* __restrict__ Wfc, const float* __restrict__ bfc,
                        float* __restrict__ out, int G) {
    int g = blockIdx.x;
    int t = threadIdx.x;           // 128 threads
    float c = fmaxf(g_cnt[g], 1.0f);
    float val = (g_pool[(size_t)g * 128 + t] / c) * Wfc[t];
#pragma unroll
    for (int o = 16; o > 0; o >>= 1) val += __shfl_down_sync(0xffffffffu, val, o);
    __shared__ float sred[4];
    int w = t >> 5;
    if ((t & 31) == 0) sred[w] = val;
    __syncthreads();
    if (t == 0) out[g] = sred[0] + sred[1] + sred[2] + sred[3] + bfc[0];
}

// ---------------------------------------------------------------------------
extern "C" void kernel_launch(void* const* d_in, const int* in_sizes, int n_in,
                              void* d_out, int out_size) {
    const float* x     = (const float*)d_in[0];
    const int*   ei    = (const int*)d_in[1];    // int32 in harness (NOT int64!)
    const int*   batch = (const int*)d_in[2];    // int32 in harness
    const float* W1    = (const float*)d_in[3];
    const float* b1    = (const float*)d_in[4];
    const float* W2    = (const float*)d_in[5];
    const float* b2    = (const float*)d_in[6];
    const float* Wfc   = (const float*)d_in[7];
    const float* bfc   = (const float*)d_in[8];
    float* out = (float*)d_out;

    int N = in_sizes[0] / HDIM;
    int E = in_sizes[1] / 2;
    int G = out_size;

    // Resolve scratch symbol addresses on the HOST. Not stream-ordered, not an
    // allocation; graph-capture-safe and deterministic.
    float *buf1, *buf2;
    cudaGetSymbolAddress((void**)&buf1, g_buf1);
    cudaGetSymbolAddress((void**)&buf2, g_buf2);

    cudaFuncSetAttribute(k_gemm, cudaFuncAttributeMaxDynamicSharedMemorySize,
                         (128 * 128 + 64 * 128) * (int)sizeof(float));

    int initN = N > G * HDIM ? N : G * HDIM;

    k_init<<<(initN + 255) / 256, 256>>>(N, G);
    k_edges_deg<<<(E + 255) / 256, 256>>>(ei, E);
    k_dis<<<(N + 255) / 256, 256>>>(batch, N);
    k_norm<<<(E + 255) / 256, 256>>>(E);

    int gemmGrid = (N + 63) / 64;
    size_t smem = (128 * 128 + 64 * 128) * sizeof(float);
    int vecN = N * 32;                     // float4 count
    int scatThreads = E * 32;
    int nodeThreads = N * 32;

    // ---- layer 1 ----
    k_gemm<<<gemmGrid, 256, smem>>>(x, W1, buf1, N);
    k_self<<<(vecN + 255) / 256, 256>>>(buf1, buf2, N);
    k_scatter<<<(scatThreads + 255) / 256, 256>>>(buf1, buf2, E);
    k_relu_bias<<<(vecN + 255) / 256, 256>>>(buf2, b1, N);

    // ---- layer 2 ----
    k_gemm<<<gemmGrid, 256, smem>>>(buf2, W2, buf1, N);
    k_self<<<(vecN + 255) / 256, 256>>>(buf1, buf2, N);
    k_scatter<<<(scatThreads + 255) / 256, 256>>>(buf1, buf2, E);
    k_relu_pool<<<(nodeThreads + 255) / 256, 256>>>(buf2, b2, batch, N);

    // ---- readout ----
    k_final<<<G, 128>>>(Wfc, bfc, out, G);
}

// round 5
// speedup vs baseline: 1.9020x; 1.9020x over previous
#include <cuda_runtime.h>
#include <cstdint>

// Problem shapes (fixed by the dataset)
#define NMAX 100000
#define EMAX 600000
#define HDIM 128
#define GMAXX 512
#define SCAN_BLK 2048          // 256 threads x 8 elems

// Scratch (allocation-free rule: __device__ globals)
__device__ float g_buf1[(size_t)NMAX * HDIM];   // GEMM outputs
__device__ float g_buf2[(size_t)NMAX * HDIM];   // hidden after layer 1
__device__ int   g_ideg[NMAX];                  // in-degree (excl. self loop)
__device__ float g_dis[NMAX];                   // rsqrt(deg+1)
__device__ int   g_src[EMAX];
__device__ int   g_dst[EMAX];
__device__ int   g_rowptr[NMAX + 1];
__device__ int   g_cursor[NMAX];
__device__ int   g_csr_src[EMAX];
__device__ float g_csr_nrm[EMAX];
__device__ int   g_blk[128];                    // scan temporaries
__device__ int   g_blkoff[128];
__device__ float g_pool[(size_t)GMAXX * HDIM];
__device__ float g_cnt[GMAXX];

// ---------------------------------------------------------------------------
__global__ void k_init(int N, int G) {
    int i = blockIdx.x * blockDim.x + threadIdx.x;
    if (i < N) g_ideg[i] = 0;
    if (i < G * HDIM) g_pool[i] = 0.0f;
    if (i < G) g_cnt[i] = 0.0f;
}

// copy edges (int32 per harness metadata), accumulate integer in-degree
__global__ void k_edges(const int* __restrict__ ei, int E) {
    int i = blockIdx.x * blockDim.x + threadIdx.x;
    if (i >= E) return;
    int s = ei[i];
    int d = ei[(size_t)E + i];
    g_src[i] = s;
    g_dst[i] = d;
    atomicAdd(&g_ideg[d], 1);
}

// ---- exclusive scan of g_ideg -> g_rowptr (3 kernels) ----
__global__ void k_scan_a(int N) {           // per-block sums
    int b = blockIdx.x, t = threadIdx.x;
    int base = b * SCAN_BLK + t * 8;
    int s = 0;
#pragma unroll
    for (int j = 0; j < 8; j++) { int i = base + j; s += (i < N) ? g_ideg[i] : 0; }
#pragma unroll
    for (int o = 16; o > 0; o >>= 1) s += __shfl_down_sync(0xffffffffu, s, o);
    __shared__ int wt[8];
    if ((t & 31) == 0) wt[t >> 5] = s;
    __syncthreads();
    if (t == 0) {
        int acc = 0;
        for (int i = 0; i < 8; i++) acc += wt[i];
        g_blk[b] = acc;
    }
}

__global__ void k_scan_b(int nblk) {        // serial exclusive scan of block sums
    if (threadIdx.x == 0) {
        int acc = 0;
        for (int i = 0; i < nblk; i++) { g_blkoff[i] = acc; acc += g_blk[i]; }
    }
}

__global__ void k_scan_c(const int* __restrict__ batch, int N, int E) {
    int b = blockIdx.x, t = threadIdx.x;
    int base = b * SCAN_BLK + t * 8;
    int pre[8];
    int s = 0;
#pragma unroll
    for (int j = 0; j < 8; j++) {
        int i = base + j;
        int v = (i < N) ? g_ideg[i] : 0;
        pre[j] = s; s += v;
    }
    int lane = t & 31, w = t >> 5;
    int incl = s;
#pragma unroll
    for (int o = 1; o < 32; o <<= 1) {
        int x = __shfl_up_sync(0xffffffffu, incl, o);
        if (lane >= o) incl += x;
    }
    __shared__ int wt[8], wb[8];
    if (lane == 31) wt[w] = incl;
    __syncthreads();
    if (t == 0) {
        int acc = 0;
        for (int i = 0; i < 8; i++) { wb[i] = acc; acc += wt[i]; }
    }
    __syncthreads();
    int thr_excl = wb[w] + incl - s;
    int gbase = g_blkoff[b] + thr_excl;
#pragma unroll
    for (int j = 0; j < 8; j++) {
        int i = base + j;
        if (i < N) {
            int rp = gbase + pre[j];
            g_rowptr[i] = rp;
            g_cursor[i] = rp;
            g_dis[i] = rsqrtf((float)(g_ideg[i] + 1));
            atomicAdd(&g_cnt[batch[i]], 1.0f);
        }
    }
    if (b == 0 && t == 0) g_rowptr[N] = E;
}

// fill CSR buckets (norm computed here; reused by both layers)
__global__ void k_fill(int E) {
    int e = blockIdx.x * blockDim.x + threadIdx.x;
    if (e >= E) return;
    int s = g_src[e], d = g_dst[e];
    int pos = atomicAdd(&g_cursor[d], 1);
    g_csr_src[pos] = s;
    g_csr_nrm[pos] = g_dis[s] * g_dis[d];
}

// ---------------------------------------------------------------------------
// GEMM: C[N,128] = A[N,128] @ W[128,128].  64-row blocks, full W in smem.
__global__ void k_gemm(const float* __restrict__ A, const float* __restrict__ Wm,
                       float* __restrict__ C, int N) {
    extern __shared__ float sh[];
    float* sW = sh;                 // 128*128
    float* sA = sh + 128 * 128;     // 64*128
    int tid = threadIdx.x;
    int row0 = blockIdx.x * 64;

    const float4* W4 = (const float4*)Wm;
    float4* sW4 = (float4*)sW;
#pragma unroll
    for (int i = 0; i < 16; i++) sW4[tid + 256 * i] = W4[tid + 256 * i];

    const float4* A4 = (const float4*)A;
    float4* sA4 = (float4*)sA;
#pragma unroll
    for (int i = 0; i < 8; i++) {
        int idx = tid + 256 * i;
        int r = idx >> 5;
        int c4 = idx & 31;
        float4 v = make_float4(0.f, 0.f, 0.f, 0.f);
        if (row0 + r < N) v = A4[(size_t)(row0 + r) * 32 + c4];
        sA4[idx] = v;
    }
    __syncthreads();

    int ty = tid >> 5;
    int tx = tid & 31;
    float acc[8][4];
#pragma unroll
    for (int i = 0; i < 8; i++)
#pragma unroll
        for (int j = 0; j < 4; j++) acc[i][j] = 0.f;

#pragma unroll 4
    for (int k = 0; k < 128; k++) {
        float4 w = ((const float4*)(sW + (size_t)k * 128))[tx];
#pragma unroll
        for (int i = 0; i < 8; i++) {
            float a = sA[(size_t)(ty + i * 8) * 128 + k];
            acc[i][0] += a * w.x;
            acc[i][1] += a * w.y;
            acc[i][2] += a * w.z;
            acc[i][3] += a * w.w;
        }
    }

#pragma unroll
    for (int i = 0; i < 8; i++) {
        int r = row0 + ty + i * 8;
        if (r < N)
            ((float4*)(C + (size_t)r * 128))[tx] =
                make_float4(acc[i][0], acc[i][1], acc[i][2], acc[i][3]);
    }
}

// ---------------------------------------------------------------------------
// Gather-side aggregation (atomic-free): one warp per node.
// acc = dis[n]^2 * gm[n] + sum_{e in CSR[n]} nrm[e] * gm[src[e]]
// epilogue: +bias, relu; layer1 stores to out, layer2 accumulates to pool.
template <int POOL>
__global__ void k_agg(const float* __restrict__ gm, const float* __restrict__ bias,
                      float* __restrict__ outb, const int* __restrict__ batch, int N) {
    int n = (blockIdx.x * blockDim.x + threadIdx.x) >> 5;
    int lane = threadIdx.x & 31;
    if (n >= N) return;

    float selfw = g_dis[n];
    selfw *= selfw;
    const float4* gm4 = (const float4*)gm;
    float4 acc = gm4[(size_t)n * 32 + lane];
    acc.x *= selfw; acc.y *= selfw; acc.z *= selfw; acc.w *= selfw;

    int beg = g_rowptr[n], end = g_rowptr[n + 1];
    for (int e = beg; e < end; e++) {
        int s = g_csr_src[e];        // uniform across warp -> broadcast
        float wn = g_csr_nrm[e];
        float4 v = gm4[(size_t)s * 32 + lane];
        acc.x += v.x * wn;
        acc.y += v.y * wn;
        acc.z += v.z * wn;
        acc.w += v.w * wn;
    }

    float4 b = ((const float4*)bias)[lane];
    acc.x = fmaxf(acc.x + b.x, 0.f);
    acc.y = fmaxf(acc.y + b.y, 0.f);
    acc.z = fmaxf(acc.z + b.z, 0.f);
    acc.w = fmaxf(acc.w + b.w, 0.f);

    if (POOL) {
        int g = batch[n];
        float* p = g_pool + (size_t)g * 128 + lane * 4;
        atomicAdd(p + 0, acc.x);
        atomicAdd(p + 1, acc.y);
        atomicAdd(p + 2, acc.z);
        atomicAdd(p + 3, acc.w);
    } else {
        ((float4*)outb)[(size_t)n * 32 + lane] = acc;
    }
}

// final: out[g] = (pool[g]/cnt[g]) . Wfc + bfc
__global__ void k_final(const float* __restrict__ Wfc, const float* __restrict__ bfc,
                        float* __restrict__ out, int G) {
    int g = blockIdx.x;
    int t = threadIdx.x;           // 128 threads
    float c = fmaxf(g_cnt[g], 1.0f);
    float val = (g_pool[(size_t)g * 128 + t] / c) * Wfc[t];
#pragma unroll
    for (int o = 16; o > 0; o >>= 1) val += __shfl_down_sync(0xffffffffu, val, o);
    __shared__ float sred[4];
    int w = t >> 5;
    if ((t & 31) == 0) sred[w] = val;
    __syncthreads();
    if (t == 0) out[g] = sred[0] + sred[1] + sred[2] + sred[3] + bfc[0];
}

// ---------------------------------------------------------------------------
extern "C" void kernel_launch(void* const* d_in, const int* in_sizes, int n_in,
                              void* d_out, int out_size) {
    const float* x     = (const float*)d_in[0];
    const int*   ei    = (const int*)d_in[1];    // int32 in harness
    const int*   batch = (const int*)d_in[2];    // int32 in harness
    const float* W1    = (const float*)d_in[3];
    const float* b1    = (const float*)d_in[4];
    const float* W2    = (const float*)d_in[5];
    const float* b2    = (const float*)d_in[6];
    const float* Wfc   = (const float*)d_in[7];
    const float* bfc   = (const float*)d_in[8];
    float* out = (float*)d_out;

    int N = in_sizes[0] / HDIM;
    int E = in_sizes[1] / 2;
    int G = out_size;

    float *buf1, *buf2;
    cudaGetSymbolAddress((void**)&buf1, g_buf1);
    cudaGetSymbolAddress((void**)&buf2, g_buf2);

    cudaFuncSetAttribute(k_gemm, cudaFuncAttributeMaxDynamicSharedMemorySize,
                         (128 * 128 + 64 * 128) * (int)sizeof(float));

    int initN = N > G * HDIM ? N : G * HDIM;
    int nblk = (N + SCAN_BLK - 1) / SCAN_BLK;

    // ---- graph prep: degrees, scan -> CSR ----
    k_init<<<(initN + 255) / 256, 256>>>(N, G);
    k_edges<<<(E + 255) / 256, 256>>>(ei, E);
    k_scan_a<<<nblk, 256>>>(N);
    k_scan_b<<<1, 32>>>(nblk);
    k_scan_c<<<nblk, 256>>>(batch, N, E);
    k_fill<<<(E + 255) / 256, 256>>>(E);

    int gemmGrid = (N + 63) / 64;
    size_t smem = (128 * 128 + 64 * 128) * sizeof(float);
    int aggBlocks = (N * 32 + 255) / 256;

    // ---- layer 1 ----
    k_gemm<<<gemmGrid, 256, smem>>>(x, W1, buf1, N);
    k_agg<0><<<aggBlocks, 256>>>(buf1, b1, buf2, batch, N);

    // ---- layer 2 (pool fused into aggregation epilogue) ----
    k_gemm<<<gemmGrid, 256, smem>>>(buf2, W2, buf1, N);
    k_agg<1><<<aggBlocks, 256>>>(buf1, b2, nullptr, batch, N);

    // ---- readout ----
    k_final<<<G, 128>>>(Wfc, bfc, out, G);
}

// round 6
// speedup vs baseline: 1.9935x; 1.0481x over previous
#include <cuda_runtime.h>
#include <cstdint>

// Problem shapes (fixed by the dataset)
#define NMAX 100000
#define EMAX 600000
#define HDIM 128
#define GMAXX 512
#define SCAN_BLK 2048          // 256 threads x 8 elems

#define LDA 132                // A-tile smem stride (pad 4: conflict-free A frags)
#define LDW 136                // W-tile smem stride (pad 8: conflict-free B frags)

// Scratch (allocation-free rule: __device__ globals)
__device__ float g_buf1[(size_t)NMAX * HDIM];   // GEMM outputs
__device__ float g_buf2[(size_t)NMAX * HDIM];   // hidden after layer 1
__device__ int   g_ideg[NMAX];                  // in-degree (excl. self loop)
__device__ float g_dis[NMAX];                   // rsqrt(deg+1)
__device__ int   g_src[EMAX];
__device__ int   g_dst[EMAX];
__device__ int   g_rowptr[NMAX + 1];
__device__ int   g_cursor[NMAX];
__device__ int   g_csr_src[EMAX];
__device__ float g_csr_nrm[EMAX];
__device__ int   g_blk[128];                    // scan temporaries
__device__ float g_pool[(size_t)GMAXX * HDIM];
__device__ float g_cnt[GMAXX];

// ---------------------------------------------------------------------------
__global__ void k_init(int N, int G) {
    int i = blockIdx.x * blockDim.x + threadIdx.x;
    if (i < N) g_ideg[i] = 0;
    if (i < G * HDIM) g_pool[i] = 0.0f;
    if (i < G) g_cnt[i] = 0.0f;
}

// copy edges (int32 per harness metadata), accumulate integer in-degree
__global__ void k_edges(const int* __restrict__ ei, int E) {
    int i = blockIdx.x * blockDim.x + threadIdx.x;
    if (i >= E) return;
    int s = ei[i];
    int d = ei[(size_t)E + i];
    g_src[i] = s;
    g_dst[i] = d;
    atomicAdd(&g_ideg[d], 1);
}

// ---- exclusive scan of g_ideg -> g_rowptr (2 kernels) ----
__global__ void k_scan_a(int N) {           // per-block sums
    int b = blockIdx.x, t = threadIdx.x;
    int base = b * SCAN_BLK + t * 8;
    int s = 0;
#pragma unroll
    for (int j = 0; j < 8; j++) { int i = base + j; s += (i < N) ? g_ideg[i] : 0; }
#pragma unroll
    for (int o = 16; o > 0; o >>= 1) s += __shfl_down_sync(0xffffffffu, s, o);
    __shared__ int wt[8];
    if ((t & 31) == 0) wt[t >> 5] = s;
    __syncthreads();
    if (t == 0) {
        int acc = 0;
        for (int i = 0; i < 8; i++) acc += wt[i];
        g_blk[b] = acc;
    }
}

__global__ void k_scan_c(const int* __restrict__ batch, int N, int E) {
    int b = blockIdx.x, t = threadIdx.x;
    __shared__ int blkoff;
    if (t == 0) {                       // per-block serial prefix over <=49 blocks
        int acc = 0;
        for (int i = 0; i < b; i++) acc += g_blk[i];
        blkoff = acc;
    }
    int base = b * SCAN_BLK + t * 8;
    int pre[8];
    int s = 0;
#pragma unroll
    for (int j = 0; j < 8; j++) {
        int i = base + j;
        int v = (i < N) ? g_ideg[i] : 0;
        pre[j] = s; s += v;
    }
    int lane = t & 31, w = t >> 5;
    int incl = s;
#pragma unroll
    for (int o = 1; o < 32; o <<= 1) {
        int x = __shfl_up_sync(0xffffffffu, incl, o);
        if (lane >= o) incl += x;
    }
    __shared__ int wt[8], wb[8];
    if (lane == 31) wt[w] = incl;
    __syncthreads();
    if (t == 0) {
        int acc = 0;
        for (int i = 0; i < 8; i++) { wb[i] = acc; acc += wt[i]; }
    }
    __syncthreads();
    int thr_excl = wb[w] + incl - s;
    int gbase = blkoff + thr_excl;
#pragma unroll
    for (int j = 0; j < 8; j++) {
        int i = base + j;
        if (i < N) {
            int rp = gbase + pre[j];
            g_rowptr[i] = rp;
            g_cursor[i] = rp;
            g_dis[i] = rsqrtf((float)(g_ideg[i] + 1));
            atomicAdd(&g_cnt[batch[i]], 1.0f);
        }
    }
    if (b == 0 && t == 0) g_rowptr[N] = E;
}

// fill CSR buckets (norm computed here; reused by both layers)
__global__ void k_fill(int E) {
    int e = blockIdx.x * blockDim.x + threadIdx.x;
    if (e >= E) return;
    int s = g_src[e], d = g_dst[e];
    int pos = atomicAdd(&g_cursor[d], 1);
    g_csr_src[pos] = s;
    g_csr_nrm[pos] = g_dis[s] * g_dis[d];
}

// ---------------------------------------------------------------------------
// 3xTF32 GEMM: C[N,128] = A[N,128] @ W[128,128], fp32-grade accuracy.
// Block: 128 rows x 128 cols, 256 threads (8 warps, 2x4), warp tile 64x32.
// mma.sync.aligned.m16n8k8.row.col.f32.tf32.tf32.f32 with Dekker split:
//   a = hi + lo;  C += ah*bh + ah*bl + al*bh   (error ~2^-24)
__device__ __forceinline__ uint32_t f2tf32(float x) {
    uint32_t r;
    asm("cvt.rna.tf32.f32 %0, %1;" : "=r"(r) : "f"(x));
    return r;
}
__device__ __forceinline__ void split_tf32(float x, uint32_t& hi, uint32_t& lo) {
    hi = f2tf32(x);
    lo = f2tf32(x - __uint_as_float(hi));
}
__device__ __forceinline__ void mma_tf32(float* c, const uint32_t* a, const uint32_t* b) {
    asm volatile(
        "mma.sync.aligned.m16n8k8.row.col.f32.tf32.tf32.f32 "
        "{%0,%1,%2,%3}, {%4,%5,%6,%7}, {%8,%9}, {%0,%1,%2,%3};"
        : "+f"(c[0]), "+f"(c[1]), "+f"(c[2]), "+f"(c[3])
        : "r"(a[0]), "r"(a[1]), "r"(a[2]), "r"(a[3]), "r"(b[0]), "r"(b[1]));
}

__global__ void k_gemm_tf32(const float* __restrict__ A, const float* __restrict__ Wm,
                            float* __restrict__ C, int N) {
    extern __shared__ float sh[];
    float* sW = sh;                   // 128 x LDW
    float* sA = sh + 128 * LDW;       // 128 x LDA
    int tid = threadIdx.x;
    int row0 = blockIdx.x * 128;

    // load W [k][n] and A tile, 16 float4 each per thread
    const float4* W4 = (const float4*)Wm;
    const float4* A4 = (const float4*)A;
#pragma unroll
    for (int i = 0; i < 16; i++) {
        int idx = tid + 256 * i;       // 0..4095
        int r = idx >> 5;              // 0..127
        int c4 = idx & 31;
        *(float4*)&sW[r * LDW + c4 * 4] = W4[idx];
        float4 v = make_float4(0.f, 0.f, 0.f, 0.f);
        if (row0 + r < N) v = A4[(size_t)(row0 + r) * 32 + c4];
        *(float4*)&sA[r * LDA + c4 * 4] = v;
    }
    __syncthreads();

    int wid = tid >> 5, lane = tid & 31;
    int gid = lane >> 2, tig = lane & 3;
    int mbase = (wid >> 2) * 64;       // warp_m in {0,1}
    int nbase = (wid & 3) * 32;        // warp_n in {0..3}

    float acc[4][4][4];
#pragma unroll
    for (int i = 0; i < 4; i++)
#pragma unroll
        for (int j = 0; j < 4; j++)
#pragma unroll
            for (int r = 0; r < 4; r++) acc[i][j][r] = 0.f;

#pragma unroll
    for (int kt = 0; kt < 16; kt++) {
        int k0 = kt * 8;
        uint32_t bh[4][2], bl[4][2];
#pragma unroll
        for (int nt = 0; nt < 4; nt++) {
            int ncol = nbase + nt * 8 + gid;
            float b0f = sW[(k0 + tig) * LDW + ncol];
            float b1f = sW[(k0 + tig + 4) * LDW + ncol];
            split_tf32(b0f, bh[nt][0], bl[nt][0]);
            split_tf32(b1f, bh[nt][1], bl[nt][1]);
        }
#pragma unroll
        for (int mt = 0; mt < 4; mt++) {
            int r0 = mbase + mt * 16 + gid;
            float a0f = sA[r0 * LDA + k0 + tig];
            float a1f = sA[(r0 + 8) * LDA + k0 + tig];
            float a2f = sA[r0 * LDA + k0 + tig + 4];
            float a3f = sA[(r0 + 8) * LDA + k0 + tig + 4];
            uint32_t ah[4], al[4];
            split_tf32(a0f, ah[0], al[0]);
            split_tf32(a1f, ah[1], al[1]);
            split_tf32(a2f, ah[2], al[2]);
            split_tf32(a3f, ah[3], al[3]);
#pragma unroll
            for (int nt = 0; nt < 4; nt++) {
                mma_tf32(acc[mt][nt], ah, bh[nt]);
                mma_tf32(acc[mt][nt], ah, bl[nt]);
                mma_tf32(acc[mt][nt], al, bh[nt]);
            }
        }
    }

    // epilogue: c0,c1 -> (row, 2*tig), c2,c3 -> (row+8, 2*tig)
#pragma unroll
    for (int mt = 0; mt < 4; mt++) {
#pragma unroll
        for (int nt = 0; nt < 4; nt++) {
            int r = row0 + mbase + mt * 16 + gid;
            int c = nbase + nt * 8 + 2 * tig;
            if (r < N)
                *(float2*)&C[(size_t)r * 128 + c] =
                    make_float2(acc[mt][nt][0], acc[mt][nt][1]);
            if (r + 8 < N)
                *(float2*)&C[(size_t)(r + 8) * 128 + c] =
                    make_float2(acc[mt][nt][2], acc[mt][nt][3]);
        }
    }
}

// ---------------------------------------------------------------------------
// Gather-side aggregation (atomic-free): one warp per node.
template <int POOL>
__global__ void k_agg(const float* __restrict__ gm, const float* __restrict__ bias,
                      float* __restrict__ outb, const int* __restrict__ batch, int N) {
    int n = (blockIdx.x * blockDim.x + threadIdx.x) >> 5;
    int lane = threadIdx.x & 31;
    if (n >= N) return;

    float selfw = g_dis[n];
    selfw *= selfw;
    const float4* gm4 = (const float4*)gm;
    float4 acc = gm4[(size_t)n * 32 + lane];
    acc.x *= selfw; acc.y *= selfw; acc.z *= selfw; acc.w *= selfw;

    int beg = g_rowptr[n], end = g_rowptr[n + 1];
    for (int e = beg; e < end; e++) {
        int s = g_csr_src[e];
        float wn = g_csr_nrm[e];
        float4 v = gm4[(size_t)s * 32 + lane];
        acc.x += v.x * wn;
        acc.y += v.y * wn;
        acc.z += v.z * wn;
        acc.w += v.w * wn;
    }

    float4 b = ((const float4*)bias)[lane];
    acc.x = fmaxf(acc.x + b.x, 0.f);
    acc.y = fmaxf(acc.y + b.y, 0.f);
    acc.z = fmaxf(acc.z + b.z, 0.f);
    acc.w = fmaxf(acc.w + b.w, 0.f);

    if (POOL) {
        int g = batch[n];
        float* p = g_pool + (size_t)g * 128 + lane * 4;
        atomicAdd(p + 0, acc.x);
        atomicAdd(p + 1, acc.y);
        atomicAdd(p + 2, acc.z);
        atomicAdd(p + 3, acc.w);
    } else {
        ((float4*)outb)[(size_t)n * 32 + lane] = acc;
    }
}

// final: out[g] = (pool[g]/cnt[g]) . Wfc + bfc
__global__ void k_final(const float* __restrict__ Wfc, const float* __restrict__ bfc,
                        float* __restrict__ out, int G) {
    int g = blockIdx.x;
    int t = threadIdx.x;           // 128 threads
    float c = fmaxf(g_cnt[g], 1.0f);
    float val = (g_pool[(size_t)g * 128 + t] / c) * Wfc[t];
#pragma unroll
    for (int o = 16; o > 0; o >>= 1) val += __shfl_down_sync(0xffffffffu, val, o);
    __shared__ float sred[4];
    int w = t >> 5;
    if ((t & 31) == 0) sred[w] = val;
    __syncthreads();
    if (t == 0) out[g] = sred[0] + sred[1] + sred[2] + sred[3] + bfc[0];
}

// ---------------------------------------------------------------------------
extern "C" void kernel_launch(void* const* d_in, const int* in_sizes, int n_in,
                              void* d_out, int out_size) {
    const float* x     = (const float*)d_in[0];
    const int*   ei    = (const int*)d_in[1];    // int32 in harness
    const int*   batch = (const int*)d_in[2];    // int32 in harness
    const float* W1    = (const float*)d_in[3];
    const float* b1    = (const float*)d_in[4];
    const float* W2    = (const float*)d_in[5];
    const float* b2    = (const float*)d_in[6];
    const float* Wfc   = (const float*)d_in[7];
    const float* bfc   = (const float*)d_in[8];
    float* out = (float*)d_out;

    int N = in_sizes[0] / HDIM;
    int E = in_sizes[1] / 2;
    int G = out_size;

    float *buf1, *buf2;
    cudaGetSymbolAddress((void**)&buf1, g_buf1);
    cudaGetSymbolAddress((void**)&buf2, g_buf2);

    size_t gsmem = (size_t)(128 * LDW + 128 * LDA) * sizeof(float);   // ~137 KB
    cudaFuncSetAttribute(k_gemm_tf32, cudaFuncAttributeMaxDynamicSharedMemorySize,
                         (int)gsmem);

    int initN = N > G * HDIM ? N : G * HDIM;
    int nblk = (N + SCAN_BLK - 1) / SCAN_BLK;

    // ---- graph prep: degrees, scan -> CSR ----
    k_init<<<(initN + 255) / 256, 256>>>(N, G);
    k_edges<<<(E + 255) / 256, 256>>>(ei, E);
    k_scan_a<<<nblk, 256>>>(N);
    k_scan_c<<<nblk, 256>>>(batch, N, E);
    k_fill<<<(E + 255) / 256, 256>>>(E);

    int gemmGrid = (N + 127) / 128;
    int aggBlocks = (N * 32 + 255) / 256;

    // ---- layer 1 ----
    k_gemm_tf32<<<gemmGrid, 256, gsmem>>>(x, W1, buf1, N);
    k_agg<0><<<aggBlocks, 256>>>(buf1, b1, buf2, batch, N);

    // ---- layer 2 (pool fused into aggregation epilogue) ----
    k_gemm_tf32<<<gemmGrid, 256, gsmem>>>(buf2, W2, buf1, N);
    k_agg<1><<<aggBlocks, 256>>>(buf1, b2, nullptr, batch, N);

    // ---- readout ----
    k_final<<<G, 128>>>(Wfc, bfc, out, G);
}